// round 15
// baseline (speedup 1.0000x reference)
#include <cuda_runtime.h>
#include <cstdint>

#define D 8192
#define ROWS_MAX 8192
#define THREADS 256
#define NWARPS (THREADS / 32)           // 8
#define NV4 (D / 4 / THREADS)           // 8 float4 per thread
#define BUF 512                         // SMEM candidate buffer
#define CAP 128                         // global scratch candidates per row
#define ROW_BYTES (D * 4)               // 32768

// ---- scratch (device globals are the sanctioned scratch mechanism) ----
__device__ int   g_cnt[ROWS_MAX];                // support count, or -1 => dense fallback
__device__ float g_tau[ROWS_MAX];
__device__ float g_val[ROWS_MAX * CAP];
__device__ int   g_idx[ROWS_MAX * CAP];

// ---- PTX helpers (sm_90+/sm_103a) ----
__device__ __forceinline__ uint32_t smem_u32(const void* p) {
    return (uint32_t)__cvta_generic_to_shared(p);
}
__device__ __forceinline__ void mbar_init(uint32_t mbar, uint32_t count) {
    asm volatile("mbarrier.init.shared::cta.b64 [%0], %1;" :: "r"(mbar), "r"(count) : "memory");
}
__device__ __forceinline__ void mbar_expect_tx(uint32_t mbar, uint32_t bytes) {
    asm volatile("mbarrier.arrive.expect_tx.shared::cta.b64 _, [%0], %1;"
                 :: "r"(mbar), "r"(bytes) : "memory");
}
__device__ __forceinline__ void tma_1d_g2s(uint32_t dst_smem, const void* src_gmem,
                                           uint32_t bytes, uint32_t mbar) {
    asm volatile("cp.async.bulk.shared::cluster.global.mbarrier::complete_tx::bytes "
                 "[%0], [%1], %2, [%3];"
                 :: "r"(dst_smem), "l"(src_gmem), "r"(bytes), "r"(mbar) : "memory");
}
__device__ __forceinline__ void mbar_wait(uint32_t mbar, uint32_t parity) {
    uint32_t done;
    asm volatile("{\n\t.reg .pred p;\n\t"
                 "mbarrier.try_wait.parity.acquire.cta.shared::cta.b64 p, [%1], %2;\n\t"
                 "selp.b32 %0, 1, 0, p;\n\t}"
                 : "=r"(done) : "r"(mbar), "r"(parity) : "memory");
    if (!done) {
        asm volatile("{\n\t.reg .pred P1;\n"
                     "WL_%=:\n\t"
                     "mbarrier.try_wait.parity.acquire.cta.shared::cta.b64 P1, [%0], %1, 0x989680;\n\t"
                     "@P1 bra.uni WD_%=;\n\t"
                     "bra.uni WL_%=;\n"
                     "WD_%=:\n\t}"
                     :: "r"(mbar), "r"(parity) : "memory");
    }
}

extern __shared__ float srow[];          // dynamic: D floats = 32 KB

// ---- Phase 1: read x, compute tau + candidate list; NO writes to out ----
__global__ __launch_bounds__(THREADS, 6)
void tau_kernel(const float* __restrict__ x, int nrows) {
    __shared__ float sbuf[BUF];
    __shared__ float swarp[NWARPS];
    __shared__ float sredf[NWARPS];
    __shared__ int   sredk[NWARPS];
    __shared__ int   s_cnt;
    __shared__ float s_tau;
    __shared__ int   s_k;
    __shared__ __align__(8) uint64_t mbar_storage;

    const int tid = threadIdx.x;
    const int lid = tid & 31;
    const int stride = gridDim.x;
    int r = blockIdx.x;
    if (r >= nrows) return;

    const uint32_t mb = smem_u32(&mbar_storage);
    const uint32_t ba = smem_u32(&srow[0]);
    const float4* __restrict__ sp4 = reinterpret_cast<const float4*>(srow);

    if (tid == 0) {
        mbar_init(mb, 1);
        s_cnt = 0;
        asm volatile("fence.mbarrier_init.release.cluster;" ::: "memory");
    }
    __syncthreads();

    if (tid == 0) {
        mbar_expect_tx(mb, ROW_BYTES);
        tma_1d_g2s(ba, x + (size_t)r * D, ROW_BYTES, mb);
    }
    uint32_t ph = 0u;

    while (true) {
        mbar_wait(mb, ph); ph ^= 1u;

        // ---- per-thread max over 32 elements ----
        float m_local;
        {
            float4 a0 = sp4[tid];
            float4 a1 = sp4[tid + THREADS];
            float4 a2 = sp4[tid + 2 * THREADS];
            float4 a3 = sp4[tid + 3 * THREADS];
            m_local = fmaxf(fmaxf(fmaxf(a0.x, a0.y), fmaxf(a0.z, a0.w)),
                            fmaxf(fmaxf(a1.x, a1.y), fmaxf(a1.z, a1.w)));
            m_local = fmaxf(m_local, fmaxf(fmaxf(a2.x, a2.y), fmaxf(a2.z, a2.w)));
            m_local = fmaxf(m_local, fmaxf(fmaxf(a3.x, a3.y), fmaxf(a3.z, a3.w)));
        }
        {
            float4 a0 = sp4[tid + 4 * THREADS];
            float4 a1 = sp4[tid + 5 * THREADS];
            float4 a2 = sp4[tid + 6 * THREADS];
            float4 a3 = sp4[tid + 7 * THREADS];
            m_local = fmaxf(m_local, fmaxf(fmaxf(a0.x, a0.y), fmaxf(a0.z, a0.w)));
            m_local = fmaxf(m_local, fmaxf(fmaxf(a1.x, a1.y), fmaxf(a1.z, a1.w)));
            m_local = fmaxf(m_local, fmaxf(fmaxf(a2.x, a2.y), fmaxf(a2.z, a2.w)));
            m_local = fmaxf(m_local, fmaxf(fmaxf(a3.x, a3.y), fmaxf(a3.z, a3.w)));
        }

        float m = m_local;
        #pragma unroll
        for (int o = 16; o > 0; o >>= 1)
            m = fmaxf(m, __shfl_xor_sync(0xffffffffu, m, o));
        if (lid == 0) swarp[tid >> 5] = m;
        __syncthreads();                 // BARRIER 1

        float mm = swarp[lid & (NWARPS - 1)];
        #pragma unroll
        for (int o = NWARPS / 2; o > 0; o >>= 1)
            mm = fmaxf(mm, __shfl_xor_sync(0xffffffffu, mm, o));
        const float thr = mm - 1.0f;     // valid lower bound on tau*

        // ---- gather candidates to SMEM + global scratch (guarded) ----
        if (m_local > thr) {
            #pragma unroll
            for (int i = 0; i < NV4; i++) {
                float4 v = sp4[tid + i * THREADS];
                int base = 4 * (tid + i * THREADS);
                #define GATHER1(u, off) do { if ((u) > thr) { \
                    int _p = atomicAdd(&s_cnt, 1); \
                    if (_p < BUF) sbuf[_p] = (u); \
                    if (_p < CAP) { g_val[(size_t)r * CAP + _p] = (u); \
                                    g_idx[(size_t)r * CAP + _p] = base + (off); } } } while (0)
                GATHER1(v.x, 0); GATHER1(v.y, 1); GATHER1(v.z, 2); GATHER1(v.w, 3);
                #undef GATHER1
            }
        }
        __syncthreads();                 // BARRIER 2: row buffer fully consumed
        const int cnt = s_cnt;
        const int rn = r + stride;
        const bool has_next = (rn < nrows);

        if (cnt <= BUF) {
            // ---- EARLY RELOAD: next row streams in under Michelot ----
            if (tid == 0 && has_next) {
                mbar_expect_tx(mb, ROW_BYTES);
                tma_1d_g2s(ba, x + (size_t)rn * D, ROW_BYTES, mb);
            }
            if (tid < 32) {
                float tau = thr;
                int prev = -1;
                for (int it = 0; it < cnt + 2; it++) {
                    float s = 0.0f; int k = 0;
                    for (int j = lid; j < cnt; j += 32) {
                        float v = sbuf[j];
                        if (v > tau) { s += v; k++; }
                    }
                    #pragma unroll
                    for (int o = 16; o > 0; o >>= 1) {
                        s += __shfl_xor_sync(0xffffffffu, s, o);
                        k += __shfl_xor_sync(0xffffffffu, k, o);
                    }
                    tau = (s - 1.0f) / (float)k;
                    if (k == prev) break;
                    prev = k;
                }
                if (lid == 0) {
                    g_tau[r] = tau;
                    g_cnt[r] = (cnt <= CAP) ? cnt : -1;   // -1 => dense fallback
                    s_cnt = 0;
                }
            }
        } else {
            // ---- dense fallback Michelot over SMEM (rare) ----
            float tau = thr;
            int prev = -1;
            for (int it = 0; it < D + 2; it++) {
                float s = 0.0f; int k = 0;
                #pragma unroll
                for (int i = 0; i < NV4; i++) {
                    float4 v = sp4[tid + i * THREADS];
                    #define ACC(u) do { if ((u) > tau) { s += (u); k++; } } while (0)
                    ACC(v.x); ACC(v.y); ACC(v.z); ACC(v.w);
                    #undef ACC
                }
                #pragma unroll
                for (int o = 16; o > 0; o >>= 1) {
                    s += __shfl_xor_sync(0xffffffffu, s, o);
                    k += __shfl_xor_sync(0xffffffffu, k, o);
                }
                if (lid == 0) { sredf[tid >> 5] = s; sredk[tid >> 5] = k; }
                __syncthreads();
                if (tid == 0) {
                    float S = 0.0f; int K = 0;
                    #pragma unroll
                    for (int w = 0; w < NWARPS; w++) { S += sredf[w]; K += sredk[w]; }
                    s_tau = (S - 1.0f) / (float)K;
                    s_k = K;
                }
                __syncthreads();
                tau = s_tau;
                int K = s_k;
                if (K == prev) break;
                prev = K;
            }
            __syncthreads();             // buffer consumed by all
            if (tid == 0) {
                g_tau[r] = tau;
                g_cnt[r] = -1;
                s_cnt = 0;
                if (has_next) {
                    mbar_expect_tx(mb, ROW_BYTES);
                    tma_1d_g2s(ba, x + (size_t)rn * D, ROW_BYTES, mb);
                }
            }
        }

        if (!has_next) break;
        r = rn;
    }
}

// ---- Phase 2: scatter support into pre-zeroed out (after memset AND phase 1) ----
__global__ __launch_bounds__(THREADS)
void scatter_kernel(const float* __restrict__ x, float* __restrict__ out, int nrows) {
    const int row = blockIdx.x * NWARPS + (threadIdx.x >> 5);
    const int lid = threadIdx.x & 31;
    if (row >= nrows) return;

    const int cnt = g_cnt[row];
    const float tau = g_tau[row];
    if (cnt >= 0) {
        // sparse: ~15 candidate (val, idx) pairs; L2-hot scratch
        float* __restrict__ orow = out + (size_t)row * D;
        for (int j = lid; j < cnt; j += 32) {
            float v = g_val[(size_t)row * CAP + j];
            if (v > tau) orow[g_idx[(size_t)row * CAP + j]] = v - tau;
        }
    } else {
        // dense fallback: re-read row, write relu(x - tau) (overwrites zeros)
        const float4* __restrict__ xr = reinterpret_cast<const float4*>(x + (size_t)row * D);
        float4* __restrict__ orow = reinterpret_cast<float4*>(out + (size_t)row * D);
        for (int j = lid; j < D / 4; j += 32) {
            float4 v = xr[j];
            v.x = fmaxf(v.x - tau, 0.0f);
            v.y = fmaxf(v.y - tau, 0.0f);
            v.z = fmaxf(v.z - tau, 0.0f);
            v.w = fmaxf(v.w - tau, 0.0f);
            orow[j] = v;
        }
    }
}

extern "C" void kernel_launch(void* const* d_in, const int* in_sizes, int n_in,
                              void* d_out, int out_size) {
    const float* x = (const float*)d_in[0];
    float* out = (float*)d_out;
    int rows = in_sizes[0] / D;          // 8192
    if (rows > ROWS_MAX) rows = ROWS_MAX;

    const int dyn_smem = D * (int)sizeof(float);   // 32 KB
    cudaFuncSetAttribute(tau_kernel,
                         cudaFuncAttributeMaxDynamicSharedMemorySize, dyn_smem);

    int dev = 0;
    cudaGetDevice(&dev);
    int nsm = 148;
    cudaDeviceGetAttribute(&nsm, cudaDevAttrMultiProcessorCount, dev);
    int grid1 = nsm * 6;
    if (grid1 > rows) grid1 = rows;
    const int grid2 = (rows + NWARPS - 1) / NWARPS;

    // fork-join: memset (writes) runs CONCURRENTLY with tau_kernel (reads).
    cudaStream_t s2;
    cudaStreamCreateWithFlags(&s2, cudaStreamNonBlocking);
    cudaEvent_t eFork, eJoin;
    cudaEventCreateWithFlags(&eFork, cudaEventDisableTiming);
    cudaEventCreateWithFlags(&eJoin, cudaEventDisableTiming);

    cudaEventRecord(eFork, 0);                 // fork from (capturing) stream
    cudaStreamWaitEvent(s2, eFork, 0);
    cudaMemsetAsync(d_out, 0, (size_t)out_size * sizeof(float), s2);   // Node A
    cudaEventRecord(eJoin, s2);                // join point

    tau_kernel<<<grid1, THREADS, dyn_smem>>>(x, rows);                 // Node B (concurrent)

    cudaStreamWaitEvent(0, eJoin, 0);          // C depends on A and B
    scatter_kernel<<<grid2, THREADS>>>(x, out, rows);                  // Node C
}

// round 16
// speedup vs baseline: 1.1440x; 1.1440x over previous
#include <cuda_runtime.h>
#include <cstdint>

#define D 8192
#define THREADS 256
#define NWARPS (THREADS / 32)           // 8
#define NV4 (D / 4 / THREADS)           // 8 float4 per thread
#define BUF 512                         // candidate buffer (floats)
#define ROW_BYTES (D * 4)               // 32768

// ---- PTX helpers (sm_90+/sm_103a) ----
__device__ __forceinline__ uint32_t smem_u32(const void* p) {
    return (uint32_t)__cvta_generic_to_shared(p);
}
__device__ __forceinline__ void mbar_init(uint32_t mbar, uint32_t count) {
    asm volatile("mbarrier.init.shared::cta.b64 [%0], %1;" :: "r"(mbar), "r"(count) : "memory");
}
__device__ __forceinline__ void mbar_expect_tx(uint32_t mbar, uint32_t bytes) {
    asm volatile("mbarrier.arrive.expect_tx.shared::cta.b64 _, [%0], %1;"
                 :: "r"(mbar), "r"(bytes) : "memory");
}
__device__ __forceinline__ void tma_1d_g2s(uint32_t dst_smem, const void* src_gmem,
                                           uint32_t bytes, uint32_t mbar) {
    asm volatile("cp.async.bulk.shared::cluster.global.mbarrier::complete_tx::bytes "
                 "[%0], [%1], %2, [%3];"
                 :: "r"(dst_smem), "l"(src_gmem), "r"(bytes), "r"(mbar) : "memory");
}
__device__ __forceinline__ void mbar_wait(uint32_t mbar, uint32_t parity) {
    uint32_t done;
    asm volatile("{\n\t.reg .pred p;\n\t"
                 "mbarrier.try_wait.parity.acquire.cta.shared::cta.b64 p, [%1], %2;\n\t"
                 "selp.b32 %0, 1, 0, p;\n\t}"
                 : "=r"(done) : "r"(mbar), "r"(parity) : "memory");
    if (!done) {
        asm volatile("{\n\t.reg .pred P1;\n"
                     "WL_%=:\n\t"
                     "mbarrier.try_wait.parity.acquire.cta.shared::cta.b64 P1, [%0], %1, 0x989680;\n\t"
                     "@P1 bra.uni WD_%=;\n\t"
                     "bra.uni WL_%=;\n"
                     "WD_%=:\n\t}"
                     :: "r"(mbar), "r"(parity) : "memory");
    }
}

// write-through STG.128: no dirty L2 line left behind (replay-friendly)
__device__ __forceinline__ void stg128_wt(float4* dst, float4 v) {
    asm volatile("st.global.wt.v4.f32 [%0], {%1, %2, %3, %4};"
                 :: "l"(dst), "f"(v.x), "f"(v.y), "f"(v.z), "f"(v.w) : "memory");
}

extern __shared__ float srow[];          // dynamic: D floats = 32 KB (single buffer)

__global__ __launch_bounds__(THREADS, 6)
void sparsemax_kernel(const float* __restrict__ x, float* __restrict__ out, int nrows) {
    __shared__ float sbuf[BUF];          // candidates > max-1
    __shared__ float swarp[NWARPS];      // block max scratch
    __shared__ float sredf[NWARPS];      // fallback sum scratch
    __shared__ int   sredk[NWARPS];      // fallback count scratch
    __shared__ int   s_cnt;
    __shared__ float s_tau;
    __shared__ int   s_k;
    __shared__ __align__(8) uint64_t mbar_storage;

    const int tid = threadIdx.x;
    const int lid = tid & 31;
    const int stride = gridDim.x;
    int r = blockIdx.x;
    if (r >= nrows) return;

    const uint32_t mb = smem_u32(&mbar_storage);
    const uint32_t ba = smem_u32(&srow[0]);
    const float4* __restrict__ sp4 = reinterpret_cast<const float4*>(srow);

    if (tid == 0) {
        mbar_init(mb, 1);
        s_cnt = 0;
        asm volatile("fence.mbarrier_init.release.cluster;" ::: "memory");
    }
    __syncthreads();

    // ---- prologue: TMA first row into the single buffer ----
    if (tid == 0) {
        mbar_expect_tx(mb, ROW_BYTES);
        tma_1d_g2s(ba, x + (size_t)r * D, ROW_BYTES, mb);
    }

    uint32_t ph = 0u;

    while (true) {
        mbar_wait(mb, ph); ph ^= 1u;

        // ---- PASS A: row max, streamed in 2 batches of 4 float4 ----
        float m_local;
        {
            float4 a0 = sp4[tid];
            float4 a1 = sp4[tid + THREADS];
            float4 a2 = sp4[tid + 2 * THREADS];
            float4 a3 = sp4[tid + 3 * THREADS];
            m_local = fmaxf(fmaxf(fmaxf(a0.x, a0.y), fmaxf(a0.z, a0.w)),
                            fmaxf(fmaxf(a1.x, a1.y), fmaxf(a1.z, a1.w)));
            m_local = fmaxf(m_local, fmaxf(fmaxf(a2.x, a2.y), fmaxf(a2.z, a2.w)));
            m_local = fmaxf(m_local, fmaxf(fmaxf(a3.x, a3.y), fmaxf(a3.z, a3.w)));
        }
        {
            float4 a0 = sp4[tid + 4 * THREADS];
            float4 a1 = sp4[tid + 5 * THREADS];
            float4 a2 = sp4[tid + 6 * THREADS];
            float4 a3 = sp4[tid + 7 * THREADS];
            m_local = fmaxf(m_local, fmaxf(fmaxf(a0.x, a0.y), fmaxf(a0.z, a0.w)));
            m_local = fmaxf(m_local, fmaxf(fmaxf(a1.x, a1.y), fmaxf(a1.z, a1.w)));
            m_local = fmaxf(m_local, fmaxf(fmaxf(a2.x, a2.y), fmaxf(a2.z, a2.w)));
            m_local = fmaxf(m_local, fmaxf(fmaxf(a3.x, a3.y), fmaxf(a3.z, a3.w)));
        }

        float m = m_local;
        #pragma unroll
        for (int o = 16; o > 0; o >>= 1)
            m = fmaxf(m, __shfl_xor_sync(0xffffffffu, m, o));
        if (lid == 0) swarp[tid >> 5] = m;
        __syncthreads();                 // BARRIER 1

        float mm = swarp[lid & (NWARPS - 1)];
        #pragma unroll
        for (int o = NWARPS / 2; o > 0; o >>= 1)
            mm = fmaxf(mm, __shfl_xor_sync(0xffffffffu, mm, o));
        const float thr = mm - 1.0f;     // valid lower bound on tau*

        // ---- PASS B: gather candidates (guard: ~handful of 256 threads) ----
        if (m_local > thr) {
            #pragma unroll
            for (int i = 0; i < NV4; i++) {
                float4 v = sp4[tid + i * THREADS];
                #define GATHER1(u) do { if ((u) > thr) { int _p = atomicAdd(&s_cnt, 1); \
                                        if (_p < BUF) sbuf[_p] = (u); } } while (0)
                GATHER1(v.x); GATHER1(v.y); GATHER1(v.z); GATHER1(v.w);
                #undef GATHER1
            }
        }
        __syncthreads();                 // BARRIER 2
        const int cnt = s_cnt;

        if (cnt <= BUF) {
            // ---- Michelot fixed-point on the tiny candidate set (warp 0) ----
            if (tid < 32) {
                float tau = thr;
                int prev = -1;
                for (int it = 0; it < cnt + 2; it++) {
                    float s = 0.0f; int k = 0;
                    for (int j = tid; j < cnt; j += 32) {
                        float v = sbuf[j];
                        if (v > tau) { s += v; k++; }
                    }
                    #pragma unroll
                    for (int o = 16; o > 0; o >>= 1) {
                        s += __shfl_xor_sync(0xffffffffu, s, o);
                        k += __shfl_xor_sync(0xffffffffu, k, o);
                    }
                    tau = (s - 1.0f) / (float)k;
                    if (k == prev) break;   // active set stable -> fixed point
                    prev = k;
                }
                if (tid == 0) s_tau = tau;
            }
        } else {
            // ---- Fallback: block-wide Michelot streaming from SMEM (rare) ----
            float tau = thr;
            int prev = -1;
            for (int it = 0; it < D + 2; it++) {
                float s = 0.0f; int k = 0;
                #pragma unroll
                for (int i = 0; i < NV4; i++) {
                    float4 v = sp4[tid + i * THREADS];
                    #define ACC(u) do { if ((u) > tau) { s += (u); k++; } } while (0)
                    ACC(v.x); ACC(v.y); ACC(v.z); ACC(v.w);
                    #undef ACC
                }
                #pragma unroll
                for (int o = 16; o > 0; o >>= 1) {
                    s += __shfl_xor_sync(0xffffffffu, s, o);
                    k += __shfl_xor_sync(0xffffffffu, k, o);
                }
                if (lid == 0) { sredf[tid >> 5] = s; sredk[tid >> 5] = k; }
                __syncthreads();
                if (tid == 0) {
                    float S = 0.0f; int K = 0;
                    #pragma unroll
                    for (int w = 0; w < NWARPS; w++) { S += sredf[w]; K += sredk[w]; }
                    s_tau = (S - 1.0f) / (float)K;
                    s_k = K;
                }
                __syncthreads();
                tau = s_tau;
                int K = s_k;
                if (K == prev) break;
                prev = K;
            }
        }
        __syncthreads();                 // BARRIER 3: s_tau visible
        const float tau = s_tau;
        if (tid == 0) s_cnt = 0;         // next gather is after next BARRIER 1

        // ---- PASS C: stream relu(x - tau) SMEM -> GMEM via write-through ----
        {
            float4* __restrict__ xout = reinterpret_cast<float4*>(out + (size_t)r * D);
            #pragma unroll
            for (int i = 0; i < NV4; i++) {
                float4 v = sp4[tid + i * THREADS];
                v.x = fmaxf(v.x - tau, 0.0f);
                v.y = fmaxf(v.y - tau, 0.0f);
                v.z = fmaxf(v.z - tau, 0.0f);
                v.w = fmaxf(v.w - tau, 0.0f);
                stg128_wt(&xout[tid + i * THREADS], v);
            }
        }
        __syncthreads();                 // BARRIER 4: buffer fully consumed

        r += stride;
        if (r >= nrows) break;
        // ---- issue TMA for the next row (buffer free by BARRIER 4) ----
        if (tid == 0) {
            mbar_expect_tx(mb, ROW_BYTES);
            tma_1d_g2s(ba, x + (size_t)r * D, ROW_BYTES, mb);
        }
    }
}

extern "C" void kernel_launch(void* const* d_in, const int* in_sizes, int n_in,
                              void* d_out, int out_size) {
    const float* x = (const float*)d_in[0];
    float* out = (float*)d_out;
    const int rows = in_sizes[0] / D;   // 8192

    const int dyn_smem = D * (int)sizeof(float);   // 32 KB single buffer
    cudaFuncSetAttribute(sparsemax_kernel,
                         cudaFuncAttributeMaxDynamicSharedMemorySize, dyn_smem);

    int dev = 0;
    cudaGetDevice(&dev);
    int nsm = 148;
    cudaDeviceGetAttribute(&nsm, cudaDevAttrMultiProcessorCount, dev);
    int grid = nsm * 6;                 // 6 CTAs/SM: 912 independent row streams
    if (grid > rows) grid = rows;

    sparsemax_kernel<<<grid, THREADS, dyn_smem>>>(x, out, rows);
}

// round 17
// speedup vs baseline: 1.1814x; 1.0326x over previous
#include <cuda_runtime.h>
#include <cstdint>

#define D 8192
#define THREADS 512
#define NWARPS (THREADS / 32)           // 16
#define BUF 1024                        // candidate buffer (floats)
#define ROW_BYTES (D * 4)               // 32768

// ---- PTX helpers (sm_90+/sm_103a) ----
__device__ __forceinline__ uint32_t smem_u32(const void* p) {
    return (uint32_t)__cvta_generic_to_shared(p);
}
__device__ __forceinline__ void mbar_init(uint32_t mbar, uint32_t count) {
    asm volatile("mbarrier.init.shared::cta.b64 [%0], %1;" :: "r"(mbar), "r"(count) : "memory");
}
__device__ __forceinline__ void mbar_expect_tx(uint32_t mbar, uint32_t bytes) {
    asm volatile("mbarrier.arrive.expect_tx.shared::cta.b64 _, [%0], %1;"
                 :: "r"(mbar), "r"(bytes) : "memory");
}
__device__ __forceinline__ void tma_1d_g2s(uint32_t dst_smem, const void* src_gmem,
                                           uint32_t bytes, uint32_t mbar) {
    asm volatile("cp.async.bulk.shared::cluster.global.mbarrier::complete_tx::bytes "
                 "[%0], [%1], %2, [%3];"
                 :: "r"(dst_smem), "l"(src_gmem), "r"(bytes), "r"(mbar) : "memory");
}
__device__ __forceinline__ void mbar_wait(uint32_t mbar, uint32_t parity) {
    uint32_t done;
    asm volatile("{\n\t.reg .pred p;\n\t"
                 "mbarrier.try_wait.parity.acquire.cta.shared::cta.b64 p, [%1], %2;\n\t"
                 "selp.b32 %0, 1, 0, p;\n\t}"
                 : "=r"(done) : "r"(mbar), "r"(parity) : "memory");
    if (!done) {
        asm volatile("{\n\t.reg .pred P1;\n"
                     "WL_%=:\n\t"
                     "mbarrier.try_wait.parity.acquire.cta.shared::cta.b64 P1, [%0], %1, 0x989680;\n\t"
                     "@P1 bra.uni WD_%=;\n\t"
                     "bra.uni WL_%=;\n"
                     "WD_%=:\n\t}"
                     :: "r"(mbar), "r"(parity) : "memory");
    }
}

extern __shared__ float srow[];          // dynamic: 2 * D floats = 64 KB (double buffer)

__global__ __launch_bounds__(THREADS, 3)
void sparsemax_kernel(const float* __restrict__ x, float* __restrict__ out, int nrows) {
    __shared__ float sbuf[BUF];          // candidates > max-1
    __shared__ float swarp[NWARPS];      // block max scratch
    __shared__ float sredf[NWARPS];      // fallback sum scratch
    __shared__ int   sredk[NWARPS];      // fallback count scratch
    __shared__ int   s_cnt;
    __shared__ float s_tau;
    __shared__ int   s_k;
    __shared__ __align__(8) uint64_t mbar_storage[2];

    const int tid = threadIdx.x;
    const int lid = tid & 31;
    const int stride = gridDim.x;
    int r = blockIdx.x;
    if (r >= nrows) return;

    const uint32_t mb0 = smem_u32(&mbar_storage[0]);
    const uint32_t mb1 = smem_u32(&mbar_storage[1]);
    const uint32_t ba0 = smem_u32(&srow[0]);
    const uint32_t ba1 = smem_u32(&srow[D]);

    if (tid == 0) {
        mbar_init(mb0, 1);
        mbar_init(mb1, 1);
        s_cnt = 0;
        asm volatile("fence.mbarrier_init.release.cluster;" ::: "memory");
    }
    __syncthreads();

    // ---- prologue: issue TMA for first row into buffer 0 ----
    if (tid == 0) {
        mbar_expect_tx(mb0, ROW_BYTES);
        tma_1d_g2s(ba0, x + (size_t)r * D, ROW_BYTES, mb0);
    }

    int cur = 0;
    uint32_t ph0 = 0u, ph1 = 0u;

    while (true) {
        const int rn = r + stride;
        const bool has_next = (rn < nrows);

        // ---- issue TMA for next row into the OTHER buffer ----
        if (has_next && tid == 0) {
            const uint32_t mbn = (cur == 0) ? mb1 : mb0;
            const uint32_t ban = (cur == 0) ? ba1 : ba0;
            mbar_expect_tx(mbn, ROW_BYTES);
            tma_1d_g2s(ban, x + (size_t)rn * D, ROW_BYTES, mbn);
        }

        // ---- wait for current buffer, consume into registers ----
        if (cur == 0) { mbar_wait(mb0, ph0); ph0 ^= 1u; }
        else          { mbar_wait(mb1, ph1); ph1 ^= 1u; }

        const float4* sp = reinterpret_cast<const float4*>(srow + (size_t)cur * D);
        float4 c0 = sp[tid];
        float4 c1 = sp[tid + THREADS];
        float4 c2 = sp[tid + 2 * THREADS];
        float4 c3 = sp[tid + 3 * THREADS];
        __syncthreads();   // all threads done reading buf[cur] -> free for next issue

        // ---- max reduction (keep per-thread local max for the gather guard) ----
        float m_local = fmaxf(fmaxf(fmaxf(c0.x, c0.y), fmaxf(c0.z, c0.w)),
                              fmaxf(fmaxf(c1.x, c1.y), fmaxf(c1.z, c1.w)));
        m_local = fmaxf(m_local, fmaxf(fmaxf(c2.x, c2.y), fmaxf(c2.z, c2.w)));
        m_local = fmaxf(m_local, fmaxf(fmaxf(c3.x, c3.y), fmaxf(c3.z, c3.w)));

        float m = m_local;
        #pragma unroll
        for (int o = 16; o > 0; o >>= 1)
            m = fmaxf(m, __shfl_xor_sync(0xffffffffu, m, o));
        if (lid == 0) swarp[tid >> 5] = m;
        __syncthreads();

        float mm = swarp[lid & (NWARPS - 1)];
        #pragma unroll
        for (int o = NWARPS / 2; o > 0; o >>= 1)
            mm = fmaxf(mm, __shfl_xor_sync(0xffffffffu, mm, o));
        const float thr = mm - 1.0f;     // valid lower bound on tau*

        // ---- gather candidates, GUARDED: ~15/512 threads enter ----
        if (m_local > thr) {
            #define GATHER1(v) do { if ((v) > thr) { int _p = atomicAdd(&s_cnt, 1); \
                                    if (_p < BUF) sbuf[_p] = (v); } } while (0)
            GATHER1(c0.x); GATHER1(c0.y); GATHER1(c0.z); GATHER1(c0.w);
            GATHER1(c1.x); GATHER1(c1.y); GATHER1(c1.z); GATHER1(c1.w);
            GATHER1(c2.x); GATHER1(c2.y); GATHER1(c2.z); GATHER1(c2.w);
            GATHER1(c3.x); GATHER1(c3.y); GATHER1(c3.z); GATHER1(c3.w);
            #undef GATHER1
        }
        __syncthreads();
        const int cnt = s_cnt;

        if (cnt <= BUF) {
            // ---- Michelot fixed-point on the tiny candidate set (warp 0) ----
            if (tid < 32) {
                float tau = thr;
                int prev = -1;
                for (int it = 0; it < cnt + 2; it++) {
                    float s = 0.0f; int k = 0;
                    for (int j = tid; j < cnt; j += 32) {
                        float v = sbuf[j];
                        if (v > tau) { s += v; k++; }
                    }
                    #pragma unroll
                    for (int o = 16; o > 0; o >>= 1) {
                        s += __shfl_xor_sync(0xffffffffu, s, o);
                        k += __shfl_xor_sync(0xffffffffu, k, o);
                    }
                    tau = (s - 1.0f) / (float)k;
                    if (k == prev) break;   // active set stable -> fixed point
                    prev = k;
                }
                if (tid == 0) s_tau = tau;
            }
            __syncthreads();
        } else {
            // ---- Fallback: block-wide Michelot over register values (rare) ----
            float tau = thr;
            int prev = -1;
            for (int it = 0; it < D + 2; it++) {
                float s = 0.0f; int k = 0;
                #define ACC(v) do { if ((v) > tau) { s += (v); k++; } } while (0)
                ACC(c0.x); ACC(c0.y); ACC(c0.z); ACC(c0.w);
                ACC(c1.x); ACC(c1.y); ACC(c1.z); ACC(c1.w);
                ACC(c2.x); ACC(c2.y); ACC(c2.z); ACC(c2.w);
                ACC(c3.x); ACC(c3.y); ACC(c3.z); ACC(c3.w);
                #undef ACC
                #pragma unroll
                for (int o = 16; o > 0; o >>= 1) {
                    s += __shfl_xor_sync(0xffffffffu, s, o);
                    k += __shfl_xor_sync(0xffffffffu, k, o);
                }
                if (lid == 0) { sredf[tid >> 5] = s; sredk[tid >> 5] = k; }
                __syncthreads();
                if (tid == 0) {
                    float S = 0.0f; int K = 0;
                    #pragma unroll
                    for (int w = 0; w < NWARPS; w++) { S += sredf[w]; K += sredk[w]; }
                    s_tau = (S - 1.0f) / (float)K;
                    s_k = K;
                }
                __syncthreads();
                tau = s_tau;
                int K = s_k;
                if (K == prev) break;
                prev = K;
            }
            __syncthreads();
        }

        if (tid == 0) s_cnt = 0;   // next gather is >=2 barriers away

        // ---- write relu(x - tau) from registers (streaming stores) ----
        const float tau = s_tau;
        c0.x = fmaxf(c0.x - tau, 0.0f); c0.y = fmaxf(c0.y - tau, 0.0f);
        c0.z = fmaxf(c0.z - tau, 0.0f); c0.w = fmaxf(c0.w - tau, 0.0f);
        c1.x = fmaxf(c1.x - tau, 0.0f); c1.y = fmaxf(c1.y - tau, 0.0f);
        c1.z = fmaxf(c1.z - tau, 0.0f); c1.w = fmaxf(c1.w - tau, 0.0f);
        c2.x = fmaxf(c2.x - tau, 0.0f); c2.y = fmaxf(c2.y - tau, 0.0f);
        c2.z = fmaxf(c2.z - tau, 0.0f); c2.w = fmaxf(c2.w - tau, 0.0f);
        c3.x = fmaxf(c3.x - tau, 0.0f); c3.y = fmaxf(c3.y - tau, 0.0f);
        c3.z = fmaxf(c3.z - tau, 0.0f); c3.w = fmaxf(c3.w - tau, 0.0f);
        float4* __restrict__ xout = reinterpret_cast<float4*>(out + (size_t)r * D);
        __stcs(&xout[tid],               c0);
        __stcs(&xout[tid + THREADS],     c1);
        __stcs(&xout[tid + 2 * THREADS], c2);
        __stcs(&xout[tid + 3 * THREADS], c3);

        if (!has_next) break;
        cur ^= 1;
        r = rn;
    }
}

extern "C" void kernel_launch(void* const* d_in, const int* in_sizes, int n_in,
                              void* d_out, int out_size) {
    const float* x = (const float*)d_in[0];
    float* out = (float*)d_out;
    const int rows = in_sizes[0] / D;   // 8192

    const int dyn_smem = 2 * D * (int)sizeof(float);   // 64 KB double buffer
    cudaFuncSetAttribute(sparsemax_kernel,
                         cudaFuncAttributeMaxDynamicSharedMemorySize, dyn_smem);

    int dev = 0;
    cudaGetDevice(&dev);
    int nsm = 148;
    cudaDeviceGetAttribute(&nsm, cudaDevAttrMultiProcessorCount, dev);
    int grid = nsm * 3;                 // 3 CTAs/SM, persistent pipeline (champion frame)
    if (grid > rows) grid = rows;

    sparsemax_kernel<<<grid, THREADS, dyn_smem>>>(x, out, rows);
}